// round 2
// baseline (speedup 1.0000x reference)
#include <cuda_runtime.h>
#include <math.h>

#define N_NODES 20000
#define N_EDGES 100000

// scratch (static __device__ per harness rules)
static __device__ float g_node[N_NODES * 512]; // [s'(128) | v'[u][i] at 128+3u+i]
static __device__ float g_h[N_EDGES * 64];

#define SILU_NORM 1.6790390826f

__device__ __forceinline__ float act(float x) {
    return SILU_NORM * x / (1.0f + __expf(-x));
}

// ---------------------------------------------------------------------------
// Kernel 1: node up-projection.  s' = s@Wus/sqrt(128), v' = einsum(v,Wuv)/sqrt(128)
// blockDim 256: two nodes at a time, weights in smem.
// ---------------------------------------------------------------------------
__global__ void __launch_bounds__(256) node_kernel(
    const float* __restrict__ nf,
    const float* __restrict__ Wus,
    const float* __restrict__ Wuv)
{
    extern __shared__ float sm[];
    float* sWs = sm;             // 16384
    float* sWv = sm + 16384;     // 16384
    float* snf = sm + 32768;     // 2*512
    int t = threadIdx.x;
    for (int i = t; i < 16384; i += 256) { sWs[i] = Wus[i]; sWv[i] = Wuv[i]; }
    __syncthreads();
    int lane = t >> 7;   // which of the 2 nodes
    int col  = t & 127;  // output channel
    const float inv = 0.08838834764831845f; // 1/sqrt(128)
    for (int base = blockIdx.x * 2; base < N_NODES; base += gridDim.x * 2) {
        int n = base + lane;
        bool ok = (n < N_NODES);
        if (ok) ((float4*)(snf + lane * 512))[col] = ((const float4*)nf)[n * 128 + col];
        __syncthreads();
        if (ok) {
            const float* row = snf + lane * 512;
            float as = 0.f, a0 = 0.f, a1 = 0.f, a2 = 0.f;
            #pragma unroll 4
            for (int u = 0; u < 128; ++u) {
                float xs = row[u];
                float x0 = row[128 + 3 * u];
                float x1 = row[128 + 3 * u + 1];
                float x2 = row[128 + 3 * u + 2];
                float ws = sWs[u * 128 + col];
                float wv = sWv[u * 128 + col];
                as += xs * ws; a0 += x0 * wv; a1 += x1 * wv; a2 += x2 * wv;
            }
            float* o = g_node + (size_t)n * 512;
            o[col]               = as * inv;
            o[128 + 3 * col]     = a0 * inv;
            o[128 + 3 * col + 1] = a1 * inv;
            o[128 + 3 * col + 2] = a2 * inv;
        }
        __syncthreads();
    }
}

// ---------------------------------------------------------------------------
// Kernel 2: edge MLP layers 0..2 -> g_h.  128 edges/CTA, 128 threads.
// thread = (edge slot es in 0..31 owning 4 edges, dim group dg owning 16 dims)
// ---------------------------------------------------------------------------
__global__ void __launch_bounds__(128) mlp_kernel(
    const float* __restrict__ ef,
    const float* __restrict__ w0,
    const float* __restrict__ w1,
    const float* __restrict__ w2)
{
    extern __shared__ float sm[];
    float* sw0 = sm;              // 512
    float* sw1 = sw0 + 512;       // 4096
    float* sw2 = sw1 + 4096;      // 4096
    float* sef = sw2 + 4096;      // 1024
    float* hA  = sef + 1024;      // 128*65
    float* hB  = hA + 128 * 65;   // 128*65

    int t = threadIdx.x;
    const float is8 = 0.35355339059327373f; // 1/sqrt(8)
    for (int i = t; i < 512; i += 128) sw0[i] = w0[i] * is8;
    for (int i = t; i < 4096; i += 128) { sw1[i] = w1[i] * 0.125f; sw2[i] = w2[i] * 0.125f; }
    int ebase = blockIdx.x * 128;
    int nvalid = N_EDGES - ebase; if (nvalid > 128) nvalid = 128;
    for (int i = t; i < 1024; i += 128)
        sef[i] = (i < nvalid * 8) ? ef[ebase * 8 + i] : 0.f;
    __syncthreads();

    int es = t & 31;
    int dg = t >> 5;
    float acc[4][16];

    // layer 0
    #pragma unroll
    for (int k = 0; k < 4; ++k)
        #pragma unroll
        for (int d = 0; d < 16; ++d) acc[k][d] = 0.f;
    #pragma unroll
    for (int u = 0; u < 8; ++u) {
        float x0 = sef[(es      ) * 8 + u];
        float x1 = sef[(es + 32) * 8 + u];
        float x2 = sef[(es + 64) * 8 + u];
        float x3 = sef[(es + 96) * 8 + u];
        #pragma unroll
        for (int d = 0; d < 16; ++d) {
            float w = sw0[u * 64 + dg * 16 + d];
            acc[0][d] += x0 * w; acc[1][d] += x1 * w; acc[2][d] += x2 * w; acc[3][d] += x3 * w;
        }
    }
    #pragma unroll
    for (int k = 0; k < 4; ++k)
        #pragma unroll
        for (int d = 0; d < 16; ++d)
            hA[(es + 32 * k) * 65 + dg * 16 + d] = act(acc[k][d]);
    __syncthreads();

    // layer 1
    #pragma unroll
    for (int k = 0; k < 4; ++k)
        #pragma unroll
        for (int d = 0; d < 16; ++d) acc[k][d] = 0.f;
    #pragma unroll 8
    for (int u = 0; u < 64; ++u) {
        float x0 = hA[(es      ) * 65 + u];
        float x1 = hA[(es + 32) * 65 + u];
        float x2 = hA[(es + 64) * 65 + u];
        float x3 = hA[(es + 96) * 65 + u];
        #pragma unroll
        for (int d = 0; d < 16; ++d) {
            float w = sw1[u * 64 + dg * 16 + d];
            acc[0][d] += x0 * w; acc[1][d] += x1 * w; acc[2][d] += x2 * w; acc[3][d] += x3 * w;
        }
    }
    #pragma unroll
    for (int k = 0; k < 4; ++k)
        #pragma unroll
        for (int d = 0; d < 16; ++d)
            hB[(es + 32 * k) * 65 + dg * 16 + d] = act(acc[k][d]);
    __syncthreads();

    // layer 2 -> g_h
    #pragma unroll
    for (int k = 0; k < 4; ++k)
        #pragma unroll
        for (int d = 0; d < 16; ++d) acc[k][d] = 0.f;
    #pragma unroll 8
    for (int u = 0; u < 64; ++u) {
        float x0 = hB[(es      ) * 65 + u];
        float x1 = hB[(es + 32) * 65 + u];
        float x2 = hB[(es + 64) * 65 + u];
        float x3 = hB[(es + 96) * 65 + u];
        #pragma unroll
        for (int d = 0; d < 16; ++d) {
            float w = sw2[u * 64 + dg * 16 + d];
            acc[0][d] += x0 * w; acc[1][d] += x1 * w; acc[2][d] += x2 * w; acc[3][d] += x3 * w;
        }
    }
    #pragma unroll
    for (int k = 0; k < 4; ++k) {
        int e = ebase + es + 32 * k;
        if (e < N_EDGES) {
            #pragma unroll
            for (int d = 0; d < 16; ++d)
                g_h[(size_t)e * 64 + dg * 16 + d] = act(acc[k][d]);
        }
    }
}

// ---------------------------------------------------------------------------
// Kernel 3: fused tpw + tensor product + output GEMMs.
// 32 edges/CTA, 256 threads (warp w owns edges 4w..4w+3; lane cg owns cols 4cg..+3)
// out_v factorization: out_v[e,n,i] = sh1_i * (P@Wv_top)[e,n] + ((Q*vs_i)@Wv_bot)[e,n]
// ---------------------------------------------------------------------------
__global__ void __launch_bounds__(256) edge_kernel(
    const float* __restrict__ ea,     // edge_attrs (E,4)
    const int*   __restrict__ eidx,   // edge_index (2,E): sender first
    const float* __restrict__ w3,     // (64,512)
    const float* __restrict__ Wos,    // (256,128)
    const float* __restrict__ Wov,    // (256,128)
    float* __restrict__ out)
{
    extern __shared__ float sm[];
    float* ssv = sm;                  // 32*512 = 16384 (gathered s'|v')
    float* sA  = ssv + 16384;         // 32*256 = 8192 (mid_s, coef folded)
    float* sP  = sA + 8192;           // 32*128 = 4096
    float* sQ  = sP + 4096;           // 32*128 = 4096
    float* sh  = sQ + 4096;           // 32*64  = 2048
    float* sW  = sh + 2048;           // 64*128 = 8192 (B staging)
    float* sea = sW + 8192;           // 128
    int*   snd = (int*)(sea + 128);   // 32

    const float C0 = 0.70710678118654752f / 128.0f;                       // sqrt(.5)/(8*16)
    const float C3 = 0.70710678118654752f / (128.0f * 1.7320508075688772f);

    int t = threadIdx.x;
    int warp = t >> 5;
    int cg = t & 31;
    int ebase = blockIdx.x * 32;

    if (t < 32) snd[t] = eidx[ebase + t];
    if (t >= 128 && t < 256) sea[t - 128] = ea[ebase * 4 + (t - 128)];
    __syncthreads();

    { // gather node rows (32 x 512 floats, 8 threads/row, float4)
        int r = t >> 3, q = t & 7;
        const float4* src = (const float4*)g_node + (size_t)snd[r] * 128;
        float4* dst = (float4*)ssv + r * 128;
        #pragma unroll
        for (int j = 0; j < 16; ++j) dst[q + 8 * j] = src[q + 8 * j];
    }
    { // h tile (512 float4)
        const float4* src = (const float4*)g_h + (size_t)ebase * 16;
        float4* dst = (float4*)sh;
        dst[t] = src[t];
        dst[t + 256] = src[t + 256];
    }
    __syncthreads();

    int e0 = warp * 4;
    const float4* w34 = (const float4*)w3;
    float4* sW4 = (float4*)sW;
    float4* ssv4 = (float4*)ssv;

    // ---- tpw chunks -> A / P / Q (coefficients folded) ----
    for (int c = 0; c < 4; ++c) {
        #pragma unroll
        for (int j = 0; j < 8; ++j) {
            int idx = t + 256 * j;           // < 2048
            int u = idx >> 5, q = idx & 31;
            sW4[idx] = w34[u * 128 + c * 32 + q];
        }
        __syncthreads();

        float acc[4][4];
        #pragma unroll
        for (int k = 0; k < 4; ++k) { acc[k][0]=0.f; acc[k][1]=0.f; acc[k][2]=0.f; acc[k][3]=0.f; }
        #pragma unroll 4
        for (int u = 0; u < 64; ++u) {
            float4 b = sW4[u * 32 + cg];
            #pragma unroll
            for (int k = 0; k < 4; ++k) {
                float a = sh[(e0 + k) * 64 + u];
                acc[k][0] += a * b.x; acc[k][1] += a * b.y;
                acc[k][2] += a * b.z; acc[k][3] += a * b.w;
            }
        }
        #pragma unroll
        for (int k = 0; k < 4; ++k) {
            int e = e0 + k;
            float s0 = sea[e * 4];
            if (c == 0) {
                float4 sv = ssv4[e * 128 + cg];
                float4 v;
                v.x = C0 * acc[k][0] * sv.x * s0; v.y = C0 * acc[k][1] * sv.y * s0;
                v.z = C0 * acc[k][2] * sv.z * s0; v.w = C0 * acc[k][3] * sv.w * s0;
                ((float4*)sA)[e * 64 + cg] = v;
            } else if (c == 1) {
                float4 sv = ssv4[e * 128 + cg];
                float4 v;
                v.x = C0 * acc[k][0] * sv.x; v.y = C0 * acc[k][1] * sv.y;
                v.z = C0 * acc[k][2] * sv.z; v.w = C0 * acc[k][3] * sv.w;
                ((float4*)sP)[e * 32 + cg] = v;
            } else if (c == 2) {
                float4 v;
                v.x = C0 * acc[k][0] * s0; v.y = C0 * acc[k][1] * s0;
                v.z = C0 * acc[k][2] * s0; v.w = C0 * acc[k][3] * s0;
                ((float4*)sQ)[e * 32 + cg] = v;
            } else {
                float s1 = sea[e * 4 + 1], s2 = sea[e * 4 + 2], s3 = sea[e * 4 + 3];
                float4 va = ssv4[e * 128 + 32 + 3 * cg];
                float4 vb = ssv4[e * 128 + 32 + 3 * cg + 1];
                float4 vc = ssv4[e * 128 + 32 + 3 * cg + 2];
                float4 v;
                v.x = C3 * acc[k][0] * (va.x * s1 + va.y * s2 + va.z * s3);
                v.y = C3 * acc[k][1] * (va.w * s1 + vb.x * s2 + vb.y * s3);
                v.z = C3 * acc[k][2] * (vb.z * s1 + vb.w * s2 + vc.x * s3);
                v.w = C3 * acc[k][3] * (vc.y * s1 + vc.z * s2 + vc.w * s3);
                ((float4*)sA)[e * 64 + 32 + cg] = v;
            }
        }
        __syncthreads();
    }

    // ---- out_s = A(32x256) @ Wos(256x128) ----
    {
        float accs[4][4];
        #pragma unroll
        for (int k = 0; k < 4; ++k) { accs[k][0]=0.f; accs[k][1]=0.f; accs[k][2]=0.f; accs[k][3]=0.f; }
        const float4* Ws4 = (const float4*)Wos;
        for (int kt = 0; kt < 4; ++kt) {
            #pragma unroll
            for (int j = 0; j < 8; ++j) { int idx = t + 256 * j; sW4[idx] = Ws4[kt * 2048 + idx]; }
            __syncthreads();
            #pragma unroll 4
            for (int u = 0; u < 64; ++u) {
                float4 b = sW4[u * 32 + cg];
                #pragma unroll
                for (int k = 0; k < 4; ++k) {
                    float a = sA[(e0 + k) * 256 + kt * 64 + u];
                    accs[k][0] += a * b.x; accs[k][1] += a * b.y;
                    accs[k][2] += a * b.z; accs[k][3] += a * b.w;
                }
            }
            __syncthreads();
        }
        #pragma unroll
        for (int k = 0; k < 4; ++k) {
            size_t e = (size_t)(ebase + e0 + k);
            ((float4*)out)[e * 128 + cg] =
                make_float4(accs[k][0], accs[k][1], accs[k][2], accs[k][3]);
        }
    }

    // ---- PV = P(32x128) @ Wv_top(128x128), QV_i = (Q*vs_i) @ Wv_bot ----
    float accp[4][4];
    #pragma unroll
    for (int k = 0; k < 4; ++k) { accp[k][0]=0.f; accp[k][1]=0.f; accp[k][2]=0.f; accp[k][3]=0.f; }
    const float4* Wv4 = (const float4*)Wov;
    for (int kt = 0; kt < 2; ++kt) {
        #pragma unroll
        for (int j = 0; j < 8; ++j) { int idx = t + 256 * j; sW4[idx] = Wv4[kt * 2048 + idx]; }
        __syncthreads();
        #pragma unroll 4
        for (int u = 0; u < 64; ++u) {
            float4 b = sW4[u * 32 + cg];
            #pragma unroll
            for (int k = 0; k < 4; ++k) {
                float a = sP[(e0 + k) * 128 + kt * 64 + u];
                accp[k][0] += a * b.x; accp[k][1] += a * b.y;
                accp[k][2] += a * b.z; accp[k][3] += a * b.w;
            }
        }
        __syncthreads();
    }
    float accq[3][4][4];
    #pragma unroll
    for (int i = 0; i < 3; ++i)
        #pragma unroll
        for (int k = 0; k < 4; ++k) { accq[i][k][0]=0.f; accq[i][k][1]=0.f; accq[i][k][2]=0.f; accq[i][k][3]=0.f; }
    for (int kt = 0; kt < 2; ++kt) {
        #pragma unroll
        for (int j = 0; j < 8; ++j) { int idx = t + 256 * j; sW4[idx] = Wv4[(128 + kt * 64) * 32 + idx]; }
        __syncthreads();
        #pragma unroll 2
        for (int u = 0; u < 64; ++u) {
            float4 b = sW4[u * 32 + cg];
            int uu = kt * 64 + u;
            #pragma unroll
            for (int k = 0; k < 4; ++k) {
                int e = e0 + k;
                float q = sQ[e * 128 + uu];
                const float* vp = &ssv[e * 512 + 128 + 3 * uu];
                float q0 = q * vp[0], q1 = q * vp[1], q2 = q * vp[2];
                accq[0][k][0] += q0 * b.x; accq[0][k][1] += q0 * b.y; accq[0][k][2] += q0 * b.z; accq[0][k][3] += q0 * b.w;
                accq[1][k][0] += q1 * b.x; accq[1][k][1] += q1 * b.y; accq[1][k][2] += q1 * b.z; accq[1][k][3] += q1 * b.w;
                accq[2][k][0] += q2 * b.x; accq[2][k][1] += q2 * b.y; accq[2][k][2] += q2 * b.z; accq[2][k][3] += q2 * b.w;
            }
        }
        __syncthreads();
    }

    // ---- combine + restage out_v through smem for coalesced stores ----
    float* vbuf = sA;   // sA(8192)+sP(4096) contiguous = 12288 floats = 32*384
    #pragma unroll
    for (int k = 0; k < 4; ++k) {
        int e = e0 + k;
        float s1 = sea[e * 4 + 1], s2 = sea[e * 4 + 2], s3 = sea[e * 4 + 3];
        #pragma unroll
        for (int j = 0; j < 4; ++j) {
            int n = cg * 4 + j;
            float pv = accp[k][j];
            vbuf[e * 384 + n * 3 + 0] = s1 * pv + accq[0][k][j];
            vbuf[e * 384 + n * 3 + 1] = s2 * pv + accq[1][k][j];
            vbuf[e * 384 + n * 3 + 2] = s3 * pv + accq[2][k][j];
        }
    }
    __syncthreads();
    float4* vb4 = (float4*)vbuf;
    #pragma unroll
    for (int j = 0; j < 12; ++j) {
        int idx = t + 256 * j;      // < 3072
        int e = idx / 96, rem = idx % 96;
        ((float4*)out)[(size_t)(ebase + e) * 128 + 32 + rem] = vb4[idx];
    }
}

// ---------------------------------------------------------------------------
extern "C" void kernel_launch(void* const* d_in, const int* in_sizes, int n_in,
                              void* d_out, int out_size) {
    const float* node_feats = (const float*)d_in[0];
    const float* edge_attrs = (const float*)d_in[1];
    const float* edge_feats = (const float*)d_in[2];
    const int*   edge_index = (const int*)d_in[3];
    const float* W_up_s  = (const float*)d_in[4];
    const float* W_up_v  = (const float*)d_in[5];
    const float* mlp_w0  = (const float*)d_in[6];
    const float* mlp_w1  = (const float*)d_in[7];
    const float* mlp_w2  = (const float*)d_in[8];
    const float* mlp_w3  = (const float*)d_in[9];
    const float* W_out_s = (const float*)d_in[10];
    const float* W_out_v = (const float*)d_in[11];
    float* out = (float*)d_out;

    size_t smem1 = (size_t)33792 * 4;   // 132 KB
    size_t smem2 = (size_t)26368 * 4;   // 103 KB
    size_t smem3 = (size_t)43200 * 4;   // 168.75 KB
    cudaFuncSetAttribute(node_kernel, cudaFuncAttributeMaxDynamicSharedMemorySize, (int)smem1);
    cudaFuncSetAttribute(mlp_kernel,  cudaFuncAttributeMaxDynamicSharedMemorySize, (int)smem2);
    cudaFuncSetAttribute(edge_kernel, cudaFuncAttributeMaxDynamicSharedMemorySize, (int)smem3);

    node_kernel<<<148, 256, smem1>>>(node_feats, W_up_s, W_up_v);
    mlp_kernel<<<(N_EDGES + 127) / 128, 128, smem2>>>(edge_feats, mlp_w0, mlp_w1, mlp_w2);
    edge_kernel<<<N_EDGES / 32, 256, smem3>>>(edge_attrs, edge_index, mlp_w3,
                                              W_out_s, W_out_v, out);
}

// round 3
// speedup vs baseline: 1.0001x; 1.0001x over previous
#include <cuda_runtime.h>
#include <math.h>

#define N_NODES 20000
#define N_EDGES 100000

// scratch (static __device__ per harness rules)
static __device__ float g_node[N_NODES * 512]; // [s'(128) | v'[u][i] at 128+3u+i]
static __device__ float g_h[N_EDGES * 64];

#define SILU_NORM 1.6790390826f

__device__ __forceinline__ float act(float x) {
    return SILU_NORM * x / (1.0f + __expf(-x));
}

// ---------------------------------------------------------------------------
// Kernel 1: node up-projection.  s' = s@Wus/sqrt(128), v' = einsum(v,Wuv)/sqrt(128)
// blockDim 256: two nodes at a time, weights in smem.
// ---------------------------------------------------------------------------
__global__ void __launch_bounds__(256) node_kernel(
    const float* __restrict__ nf,
    const float* __restrict__ Wus,
    const float* __restrict__ Wuv)
{
    extern __shared__ float sm[];
    float* sWs = sm;             // 16384
    float* sWv = sm + 16384;     // 16384
    float* snf = sm + 32768;     // 2*512
    int t = threadIdx.x;
    for (int i = t; i < 16384; i += 256) { sWs[i] = Wus[i]; sWv[i] = Wuv[i]; }
    __syncthreads();
    int lane = t >> 7;   // which of the 2 nodes
    int col  = t & 127;  // output channel
    const float inv = 0.08838834764831845f; // 1/sqrt(128)
    for (int base = blockIdx.x * 2; base < N_NODES; base += gridDim.x * 2) {
        int n = base + lane;
        bool ok = (n < N_NODES);
        if (ok) ((float4*)(snf + lane * 512))[col] = ((const float4*)nf)[n * 128 + col];
        __syncthreads();
        if (ok) {
            const float* row = snf + lane * 512;
            float as = 0.f, a0 = 0.f, a1 = 0.f, a2 = 0.f;
            #pragma unroll 4
            for (int u = 0; u < 128; ++u) {
                float xs = row[u];
                float x0 = row[128 + 3 * u];
                float x1 = row[128 + 3 * u + 1];
                float x2 = row[128 + 3 * u + 2];
                float ws = sWs[u * 128 + col];
                float wv = sWv[u * 128 + col];
                as += xs * ws; a0 += x0 * wv; a1 += x1 * wv; a2 += x2 * wv;
            }
            float* o = g_node + (size_t)n * 512;
            o[col]               = as * inv;
            o[128 + 3 * col]     = a0 * inv;
            o[128 + 3 * col + 1] = a1 * inv;
            o[128 + 3 * col + 2] = a2 * inv;
        }
        __syncthreads();
    }
}

// ---------------------------------------------------------------------------
// Kernel 2: edge MLP layers 0..2 -> g_h.  128 edges/CTA, 128 threads.
// thread = (edge slot es in 0..31 owning 4 edges, dim group dg owning 16 dims)
// ---------------------------------------------------------------------------
__global__ void __launch_bounds__(128) mlp_kernel(
    const float* __restrict__ ef,
    const float* __restrict__ w0,
    const float* __restrict__ w1,
    const float* __restrict__ w2)
{
    extern __shared__ float sm[];
    float* sw0 = sm;              // 512
    float* sw1 = sw0 + 512;       // 4096
    float* sw2 = sw1 + 4096;      // 4096
    float* sef = sw2 + 4096;      // 1024
    float* hA  = sef + 1024;      // 128*65
    float* hB  = hA + 128 * 65;   // 128*65

    int t = threadIdx.x;
    const float is8 = 0.35355339059327373f; // 1/sqrt(8)
    for (int i = t; i < 512; i += 128) sw0[i] = w0[i] * is8;
    for (int i = t; i < 4096; i += 128) { sw1[i] = w1[i] * 0.125f; sw2[i] = w2[i] * 0.125f; }
    int ebase = blockIdx.x * 128;
    int nvalid = N_EDGES - ebase; if (nvalid > 128) nvalid = 128;
    for (int i = t; i < 1024; i += 128)
        sef[i] = (i < nvalid * 8) ? ef[ebase * 8 + i] : 0.f;
    __syncthreads();

    int es = t & 31;
    int dg = t >> 5;
    float acc[4][16];

    // layer 0
    #pragma unroll
    for (int k = 0; k < 4; ++k)
        #pragma unroll
        for (int d = 0; d < 16; ++d) acc[k][d] = 0.f;
    #pragma unroll
    for (int u = 0; u < 8; ++u) {
        float x0 = sef[(es      ) * 8 + u];
        float x1 = sef[(es + 32) * 8 + u];
        float x2 = sef[(es + 64) * 8 + u];
        float x3 = sef[(es + 96) * 8 + u];
        #pragma unroll
        for (int d = 0; d < 16; ++d) {
            float w = sw0[u * 64 + dg * 16 + d];
            acc[0][d] += x0 * w; acc[1][d] += x1 * w; acc[2][d] += x2 * w; acc[3][d] += x3 * w;
        }
    }
    #pragma unroll
    for (int k = 0; k < 4; ++k)
        #pragma unroll
        for (int d = 0; d < 16; ++d)
            hA[(es + 32 * k) * 65 + dg * 16 + d] = act(acc[k][d]);
    __syncthreads();

    // layer 1
    #pragma unroll
    for (int k = 0; k < 4; ++k)
        #pragma unroll
        for (int d = 0; d < 16; ++d) acc[k][d] = 0.f;
    #pragma unroll 8
    for (int u = 0; u < 64; ++u) {
        float x0 = hA[(es      ) * 65 + u];
        float x1 = hA[(es + 32) * 65 + u];
        float x2 = hA[(es + 64) * 65 + u];
        float x3 = hA[(es + 96) * 65 + u];
        #pragma unroll
        for (int d = 0; d < 16; ++d) {
            float w = sw1[u * 64 + dg * 16 + d];
            acc[0][d] += x0 * w; acc[1][d] += x1 * w; acc[2][d] += x2 * w; acc[3][d] += x3 * w;
        }
    }
    #pragma unroll
    for (int k = 0; k < 4; ++k)
        #pragma unroll
        for (int d = 0; d < 16; ++d)
            hB[(es + 32 * k) * 65 + dg * 16 + d] = act(acc[k][d]);
    __syncthreads();

    // layer 2 -> g_h
    #pragma unroll
    for (int k = 0; k < 4; ++k)
        #pragma unroll
        for (int d = 0; d < 16; ++d) acc[k][d] = 0.f;
    #pragma unroll 8
    for (int u = 0; u < 64; ++u) {
        float x0 = hB[(es      ) * 65 + u];
        float x1 = hB[(es + 32) * 65 + u];
        float x2 = hB[(es + 64) * 65 + u];
        float x3 = hB[(es + 96) * 65 + u];
        #pragma unroll
        for (int d = 0; d < 16; ++d) {
            float w = sw2[u * 64 + dg * 16 + d];
            acc[0][d] += x0 * w; acc[1][d] += x1 * w; acc[2][d] += x2 * w; acc[3][d] += x3 * w;
        }
    }
    #pragma unroll
    for (int k = 0; k < 4; ++k) {
        int e = ebase + es + 32 * k;
        if (e < N_EDGES) {
            #pragma unroll
            for (int d = 0; d < 16; ++d)
                g_h[(size_t)e * 64 + dg * 16 + d] = act(acc[k][d]);
        }
    }
}

// ---------------------------------------------------------------------------
// Kernel 3: fused tpw + tensor product + output GEMMs.
// 32 edges/CTA, 256 threads (warp w owns edges 4w..4w+3; lane cg owns cols 4cg..+3)
// out_v factorization: out_v[e,n,i] = sh1_i * (P@Wv_top)[e,n] + ((Q*vs_i)@Wv_bot)[e,n]
// ---------------------------------------------------------------------------
__global__ void __launch_bounds__(256) edge_kernel(
    const float* __restrict__ ea,     // edge_attrs (E,4)
    const int*   __restrict__ eidx,   // edge_index (2,E): sender first
    const float* __restrict__ w3,     // (64,512)
    const float* __restrict__ Wos,    // (256,128)
    const float* __restrict__ Wov,    // (256,128)
    float* __restrict__ out)
{
    extern __shared__ float sm[];
    float* ssv = sm;                  // 32*512 = 16384 (gathered s'|v')
    float* sA  = ssv + 16384;         // 32*256 = 8192 (mid_s, coef folded)
    float* sP  = sA + 8192;           // 32*128 = 4096
    float* sQ  = sP + 4096;           // 32*128 = 4096
    float* sh  = sQ + 4096;           // 32*64  = 2048
    float* sW  = sh + 2048;           // 64*128 = 8192 (B staging)
    float* sea = sW + 8192;           // 128
    int*   snd = (int*)(sea + 128);   // 32

    const float C0 = 0.70710678118654752f / 128.0f;                       // sqrt(.5)/(8*16)
    const float C3 = 0.70710678118654752f / (128.0f * 1.7320508075688772f);

    int t = threadIdx.x;
    int warp = t >> 5;
    int cg = t & 31;
    int ebase = blockIdx.x * 32;

    if (t < 32) snd[t] = eidx[ebase + t];
    if (t >= 128 && t < 256) sea[t - 128] = ea[ebase * 4 + (t - 128)];
    __syncthreads();

    { // gather node rows (32 x 512 floats, 8 threads/row, float4)
        int r = t >> 3, q = t & 7;
        const float4* src = (const float4*)g_node + (size_t)snd[r] * 128;
        float4* dst = (float4*)ssv + r * 128;
        #pragma unroll
        for (int j = 0; j < 16; ++j) dst[q + 8 * j] = src[q + 8 * j];
    }
    { // h tile (512 float4)
        const float4* src = (const float4*)g_h + (size_t)ebase * 16;
        float4* dst = (float4*)sh;
        dst[t] = src[t];
        dst[t + 256] = src[t + 256];
    }
    __syncthreads();

    int e0 = warp * 4;
    const float4* w34 = (const float4*)w3;
    float4* sW4 = (float4*)sW;
    float4* ssv4 = (float4*)ssv;

    // ---- tpw chunks -> A / P / Q (coefficients folded) ----
    for (int c = 0; c < 4; ++c) {
        #pragma unroll
        for (int j = 0; j < 8; ++j) {
            int idx = t + 256 * j;           // < 2048
            int u = idx >> 5, q = idx & 31;
            sW4[idx] = w34[u * 128 + c * 32 + q];
        }
        __syncthreads();

        float acc[4][4];
        #pragma unroll
        for (int k = 0; k < 4; ++k) { acc[k][0]=0.f; acc[k][1]=0.f; acc[k][2]=0.f; acc[k][3]=0.f; }
        #pragma unroll 4
        for (int u = 0; u < 64; ++u) {
            float4 b = sW4[u * 32 + cg];
            #pragma unroll
            for (int k = 0; k < 4; ++k) {
                float a = sh[(e0 + k) * 64 + u];
                acc[k][0] += a * b.x; acc[k][1] += a * b.y;
                acc[k][2] += a * b.z; acc[k][3] += a * b.w;
            }
        }
        #pragma unroll
        for (int k = 0; k < 4; ++k) {
            int e = e0 + k;
            float s0 = sea[e * 4];
            if (c == 0) {
                float4 sv = ssv4[e * 128 + cg];
                float4 v;
                v.x = C0 * acc[k][0] * sv.x * s0; v.y = C0 * acc[k][1] * sv.y * s0;
                v.z = C0 * acc[k][2] * sv.z * s0; v.w = C0 * acc[k][3] * sv.w * s0;
                ((float4*)sA)[e * 64 + cg] = v;
            } else if (c == 1) {
                float4 sv = ssv4[e * 128 + cg];
                float4 v;
                v.x = C0 * acc[k][0] * sv.x; v.y = C0 * acc[k][1] * sv.y;
                v.z = C0 * acc[k][2] * sv.z; v.w = C0 * acc[k][3] * sv.w;
                ((float4*)sP)[e * 32 + cg] = v;
            } else if (c == 2) {
                float4 v;
                v.x = C0 * acc[k][0] * s0; v.y = C0 * acc[k][1] * s0;
                v.z = C0 * acc[k][2] * s0; v.w = C0 * acc[k][3] * s0;
                ((float4*)sQ)[e * 32 + cg] = v;
            } else {
                float s1 = sea[e * 4 + 1], s2 = sea[e * 4 + 2], s3 = sea[e * 4 + 3];
                float4 va = ssv4[e * 128 + 32 + 3 * cg];
                float4 vb = ssv4[e * 128 + 32 + 3 * cg + 1];
                float4 vc = ssv4[e * 128 + 32 + 3 * cg + 2];
                float4 v;
                v.x = C3 * acc[k][0] * (va.x * s1 + va.y * s2 + va.z * s3);
                v.y = C3 * acc[k][1] * (va.w * s1 + vb.x * s2 + vb.y * s3);
                v.z = C3 * acc[k][2] * (vb.z * s1 + vb.w * s2 + vc.x * s3);
                v.w = C3 * acc[k][3] * (vc.y * s1 + vc.z * s2 + vc.w * s3);
                ((float4*)sA)[e * 64 + 32 + cg] = v;
            }
        }
        __syncthreads();
    }

    // ---- out_s = A(32x256) @ Wos(256x128) ----
    {
        float accs[4][4];
        #pragma unroll
        for (int k = 0; k < 4; ++k) { accs[k][0]=0.f; accs[k][1]=0.f; accs[k][2]=0.f; accs[k][3]=0.f; }
        const float4* Ws4 = (const float4*)Wos;
        for (int kt = 0; kt < 4; ++kt) {
            #pragma unroll
            for (int j = 0; j < 8; ++j) { int idx = t + 256 * j; sW4[idx] = Ws4[kt * 2048 + idx]; }
            __syncthreads();
            #pragma unroll 4
            for (int u = 0; u < 64; ++u) {
                float4 b = sW4[u * 32 + cg];
                #pragma unroll
                for (int k = 0; k < 4; ++k) {
                    float a = sA[(e0 + k) * 256 + kt * 64 + u];
                    accs[k][0] += a * b.x; accs[k][1] += a * b.y;
                    accs[k][2] += a * b.z; accs[k][3] += a * b.w;
                }
            }
            __syncthreads();
        }
        #pragma unroll
        for (int k = 0; k < 4; ++k) {
            size_t e = (size_t)(ebase + e0 + k);
            ((float4*)out)[e * 128 + cg] =
                make_float4(accs[k][0], accs[k][1], accs[k][2], accs[k][3]);
        }
    }

    // ---- PV = P(32x128) @ Wv_top(128x128), QV_i = (Q*vs_i) @ Wv_bot ----
    float accp[4][4];
    #pragma unroll
    for (int k = 0; k < 4; ++k) { accp[k][0]=0.f; accp[k][1]=0.f; accp[k][2]=0.f; accp[k][3]=0.f; }
    const float4* Wv4 = (const float4*)Wov;
    for (int kt = 0; kt < 2; ++kt) {
        #pragma unroll
        for (int j = 0; j < 8; ++j) { int idx = t + 256 * j; sW4[idx] = Wv4[kt * 2048 + idx]; }
        __syncthreads();
        #pragma unroll 4
        for (int u = 0; u < 64; ++u) {
            float4 b = sW4[u * 32 + cg];
            #pragma unroll
            for (int k = 0; k < 4; ++k) {
                float a = sP[(e0 + k) * 128 + kt * 64 + u];
                accp[k][0] += a * b.x; accp[k][1] += a * b.y;
                accp[k][2] += a * b.z; accp[k][3] += a * b.w;
            }
        }
        __syncthreads();
    }
    float accq[3][4][4];
    #pragma unroll
    for (int i = 0; i < 3; ++i)
        #pragma unroll
        for (int k = 0; k < 4; ++k) { accq[i][k][0]=0.f; accq[i][k][1]=0.f; accq[i][k][2]=0.f; accq[i][k][3]=0.f; }
    for (int kt = 0; kt < 2; ++kt) {
        #pragma unroll
        for (int j = 0; j < 8; ++j) { int idx = t + 256 * j; sW4[idx] = Wv4[(128 + kt * 64) * 32 + idx]; }
        __syncthreads();
        #pragma unroll 2
        for (int u = 0; u < 64; ++u) {
            float4 b = sW4[u * 32 + cg];
            int uu = kt * 64 + u;
            #pragma unroll
            for (int k = 0; k < 4; ++k) {
                int e = e0 + k;
                float q = sQ[e * 128 + uu];
                const float* vp = &ssv[e * 512 + 128 + 3 * uu];
                float q0 = q * vp[0], q1 = q * vp[1], q2 = q * vp[2];
                accq[0][k][0] += q0 * b.x; accq[0][k][1] += q0 * b.y; accq[0][k][2] += q0 * b.z; accq[0][k][3] += q0 * b.w;
                accq[1][k][0] += q1 * b.x; accq[1][k][1] += q1 * b.y; accq[1][k][2] += q1 * b.z; accq[1][k][3] += q1 * b.w;
                accq[2][k][0] += q2 * b.x; accq[2][k][1] += q2 * b.y; accq[2][k][2] += q2 * b.z; accq[2][k][3] += q2 * b.w;
            }
        }
        __syncthreads();
    }

    // ---- combine + restage out_v through smem for coalesced stores ----
    float* vbuf = sA;   // sA(8192)+sP(4096) contiguous = 12288 floats = 32*384
    #pragma unroll
    for (int k = 0; k < 4; ++k) {
        int e = e0 + k;
        float s1 = sea[e * 4 + 1], s2 = sea[e * 4 + 2], s3 = sea[e * 4 + 3];
        #pragma unroll
        for (int j = 0; j < 4; ++j) {
            int n = cg * 4 + j;
            float pv = accp[k][j];
            vbuf[e * 384 + n * 3 + 0] = s1 * pv + accq[0][k][j];
            vbuf[e * 384 + n * 3 + 1] = s2 * pv + accq[1][k][j];
            vbuf[e * 384 + n * 3 + 2] = s3 * pv + accq[2][k][j];
        }
    }
    __syncthreads();
    float4* vb4 = (float4*)vbuf;
    #pragma unroll
    for (int j = 0; j < 12; ++j) {
        int idx = t + 256 * j;      // < 3072
        int e = idx / 96, rem = idx % 96;
        ((float4*)out)[(size_t)(ebase + e) * 128 + 32 + rem] = vb4[idx];
    }
}

// ---------------------------------------------------------------------------
extern "C" void kernel_launch(void* const* d_in, const int* in_sizes, int n_in,
                              void* d_out, int out_size) {
    const float* node_feats = (const float*)d_in[0];
    const float* edge_attrs = (const float*)d_in[1];
    const float* edge_feats = (const float*)d_in[2];
    const int*   edge_index = (const int*)d_in[3];
    const float* W_up_s  = (const float*)d_in[4];
    const float* W_up_v  = (const float*)d_in[5];
    const float* mlp_w0  = (const float*)d_in[6];
    const float* mlp_w1  = (const float*)d_in[7];
    const float* mlp_w2  = (const float*)d_in[8];
    const float* mlp_w3  = (const float*)d_in[9];
    const float* W_out_s = (const float*)d_in[10];
    const float* W_out_v = (const float*)d_in[11];
    float* out = (float*)d_out;

    size_t smem1 = (size_t)33792 * 4;   // 132 KB
    size_t smem2 = (size_t)26368 * 4;   // 103 KB
    size_t smem3 = (size_t)43200 * 4;   // 168.75 KB
    cudaFuncSetAttribute(node_kernel, cudaFuncAttributeMaxDynamicSharedMemorySize, (int)smem1);
    cudaFuncSetAttribute(mlp_kernel,  cudaFuncAttributeMaxDynamicSharedMemorySize, (int)smem2);
    cudaFuncSetAttribute(edge_kernel, cudaFuncAttributeMaxDynamicSharedMemorySize, (int)smem3);

    node_kernel<<<148, 256, smem1>>>(node_feats, W_up_s, W_up_v);
    mlp_kernel<<<(N_EDGES + 127) / 128, 128, smem2>>>(edge_feats, mlp_w0, mlp_w1, mlp_w2);
    edge_kernel<<<N_EDGES / 32, 256, smem3>>>(edge_attrs, edge_index, mlp_w3,
                                              W_out_s, W_out_v, out);
}